// round 10
// baseline (speedup 1.0000x reference)
#include <cuda_runtime.h>
#include <math.h>

#define BATCH 8
#define NPTS  2048
#define HCOLS 1024            // columns per block (half split)
#define LOG2E 1.4426950408889634f
#define LN2   0.6931471805599453f
#define TPB   128
#define CHUNK 16
#define SH_BYTES (HCOLS * 16) // float4 per column pair-slot = 16 KB

// dual potentials, double-buffered: [buf][s: f_ba,g_ab,f_aa,g_bb][b*NPTS + i]
__device__ float g_dual[2][4][BATCH * NPTS];
// per-half PLAIN partial sums (shifted log2 domain): [half][s][b*NPTS + r]
__device__ float g_ps[2][4][BATCH * NPTS];
// 0.5*|p|^2 per point, [0]=x rows, [1]=y rows
__device__ float g_sq[2][BATCH * NPTS];

__device__ __forceinline__ float ex2(float x) {
    float r;
    asm("ex2.approx.ftz.f32 %0, %1;" : "=f"(r) : "f"(x));
    return r;
}
__device__ __forceinline__ unsigned long long pk2(float a, float b) {
    unsigned long long u;
    asm("mov.b64 %0, {%1,%2};" : "=l"(u) : "f"(a), "f"(b));
    return u;
}
__device__ __forceinline__ void upk2(unsigned long long u, float& a, float& b) {
    asm("mov.b64 {%0,%1}, %2;" : "=f"(a), "=f"(b) : "l"(u));
}
__device__ __forceinline__ unsigned long long fma2(unsigned long long a,
                                                   unsigned long long b,
                                                   unsigned long long c) {
    unsigned long long d;
    asm("fma.rn.f32x2 %0, %1, %2, %3;" : "=l"(d) : "l"(a), "l"(b), "l"(c));
    return d;
}
__device__ __forceinline__ unsigned long long add2(unsigned long long a,
                                                   unsigned long long b) {
    unsigned long long d;
    asm("add.rn.f32x2 %0, %1, %2;" : "=l"(d) : "l"(a), "l"(b));
    return d;
}

// softmin(eps,C,h)_i = -eps * LSE_j( h_j - C_ij/eps ), C_ij = .5|r_i|^2+.5|c_j|^2 - r.c
// log2 domain, PER-ROW SHIFT instead of online max:
//   S_i = (0.5|r_i|^2 - f_prev_i) * log2e / eps   (estimate of the row's log2-LSE)
//   ssum_i = sum_j 2^(arg_ij - S_i)   -- bounded since f drifts << 115*eps*ln2/phase
//   f_new_i = f_prev_i - eps*ln2*log2(ssum_i)
// Init phase (shift=0, eps=4): raw args lie in [-11.5,-10.7] log2 -> safe unshifted.
__global__ __launch_bounds__(TPB) void sinkhorn_phase(
    const float* __restrict__ x, const float* __restrict__ y,
    float eps, float dual_scale, int shift, int rbuf)
{
    const int s = blockIdx.y;
    const int b = blockIdx.z;
    const int half   = blockIdx.x & 1;
    const int rowblk = blockIdx.x >> 1;
    const float* rows = (s == 0 || s == 2) ? x : y;
    const float* cols = (s == 0 || s == 3) ? y : x;
    const int di = (s == 0) ? 1 : (s == 1) ? 0 : s;
    const float* dual = g_dual[rbuf][di] + b * NPTS;
    const float* own  = g_dual[rbuf][s]  + b * NPTS;

    // pair-interleaved column table for packed FFMA2 (dynamic smem, 16 KB):
    // sh[2p]   = (c0a*sc, c0b*sc, c1a*sc, c1b*sc)
    // sh[2p+1] = (c2a*sc, c2b*sc, wa,     wb)      for columns (2p, 2p+1)
    extern __shared__ float4 sh[];

    const float inv_eps = 1.0f / eps;
    const float sc = inv_eps * LOG2E;
    const float logw = -logf((float)NPTS);
    const int col0 = half * HCOLS;

    for (int p = threadIdx.x; p < HCOLS / 2; p += TPB) {
        int j = col0 + 2 * p;
        const float* c = cols + (b * NPTS + j) * 3;
        float c0a = c[0], c1a = c[1], c2a = c[2];
        float c0b = c[3], c1b = c[4], c2b = c[5];
        float ha = logw + dual_scale * dual[j] * inv_eps;
        float hb = logw + dual_scale * dual[j + 1] * inv_eps;
        float wa = (ha - 0.5f * (c0a * c0a + c1a * c1a + c2a * c2a) * inv_eps) * LOG2E;
        float wb = (hb - 0.5f * (c0b * c0b + c1b * c1b + c2b * c2b) * inv_eps) * LOG2E;
        sh[2 * p]     = make_float4(c0a * sc, c0b * sc, c1a * sc, c1b * sc);
        sh[2 * p + 1] = make_float4(c2a * sc, c2b * sc, wa, wb);
    }
    __syncthreads();

    const int r = rowblk * TPB + threadIdx.x;
    const float* xr = rows + (b * NPTS + r) * 3;
    const float x0 = xr[0], x1 = xr[1], x2 = xr[2];
    const unsigned long long X0 = pk2(x0, x0);
    const unsigned long long X1 = pk2(x1, x1);
    const unsigned long long X2 = pk2(x2, x2);

    // per-row shift from previous dual value (always finite: zero-init / prior phase)
    const float sqr = 0.5f * (x0 * x0 + x1 * x1 + x2 * x2);
    const float S = shift ? (sqr - own[r]) * inv_eps * LOG2E : 0.0f;
    const unsigned long long nS2 = pk2(-S, -S);

    const ulonglong2* shu = (const ulonglong2*)sh;

    float ssum = 0.0f;

    #pragma unroll 1
    for (int j = 0; j < HCOLS; j += CHUNK) {
        // packed dots with w and -S folded in: 3 FFMA2 + 1 FADD2 per column pair
        unsigned long long d[CHUNK / 2];
        #pragma unroll
        for (int k = 0; k < CHUNK / 2; k++) {
            ulonglong2 A = shu[j + 2 * k];
            ulonglong2 B = shu[j + 2 * k + 1];
            d[k] = fma2(X0, A.x, fma2(X1, A.y, fma2(X2, B.x, add2(B.y, nS2))));
        }
        float a[CHUNK];
        #pragma unroll
        for (int k = 0; k < CHUNK / 2; k++) upk2(d[k], a[2 * k], a[2 * k + 1]);

        // 16 independent ex2 at the MUFU floor; no max, no merge
        float e[CHUNK];
        #pragma unroll
        for (int k = 0; k < CHUNK; k++) e[k] = ex2(a[k]);
        float s0 = (e[0] + e[1]) + (e[2] + e[3]);
        float s1 = (e[4] + e[5]) + (e[6] + e[7]);
        float s2 = (e[8] + e[9]) + (e[10] + e[11]);
        float s3 = (e[12] + e[13]) + (e[14] + e[15]);
        ssum += (s0 + s1) + (s2 + s3);
    }

    g_ps[half][s][b * NPTS + r] = ssum;
}

// merge the two halves, finish the softmin, apply averaging
__global__ void sinkhorn_combine(float eps, int do_avg, int shift, int rbuf, int wbuf)
{
    int idx = blockIdx.x * 256 + threadIdx.x;      // 4*BATCH*NPTS = 65536
    int s = idx >> 14;
    int rem = idx & 16383;                         // b*NPTS + r
    float sm = g_ps[0][s][rem] + g_ps[1][s][rem];
    float l2 = log2f(sm);
    float fp = g_dual[rbuf][s][rem];
    int rows_sel = (s == 0 || s == 2) ? 0 : 1;
    float fraw = shift ? fp - eps * LN2 * l2
                       : g_sq[rows_sel][rem] - eps * LN2 * l2;
    float o = do_avg ? 0.5f * (fp + fraw) : fraw;
    g_dual[wbuf][s][rem] = o;
}

__global__ void init_sq(const float* __restrict__ x, const float* __restrict__ y)
{
    int idx = blockIdx.x * 256 + threadIdx.x;      // 2*BATCH*NPTS = 32768
    int sel = idx >> 14;
    int rem = idx & 16383;
    const float* p = (sel ? y : x) + rem * 3;
    g_sq[sel][rem] = 0.5f * (p[0] * p[0] + p[1] * p[1] + p[2] * p[2]);
}

// out[b] = (1/N) * sum_i (f_ba - f_aa) + (1/M) * sum_j (g_ab - g_bb)
__global__ void sinkhorn_reduce(float* __restrict__ out, int buf)
{
    const int b = blockIdx.x;
    const int tid = threadIdx.x;
    float acc = 0.0f;
    for (int i = tid; i < NPTS; i += 256) {
        acc += g_dual[buf][0][b * NPTS + i] - g_dual[buf][2][b * NPTS + i];
        acc += g_dual[buf][1][b * NPTS + i] - g_dual[buf][3][b * NPTS + i];
    }
    __shared__ float red[256];
    red[tid] = acc;
    __syncthreads();
    for (int off = 128; off > 0; off >>= 1) {
        if (tid < off) red[tid] += red[tid + off];
        __syncthreads();
    }
    if (tid == 0) {
        float w = expf(-logf((float)NPTS));
        out[b] = red[0] * w;
    }
}

extern "C" void kernel_launch(void* const* d_in, const int* in_sizes, int n_in,
                              void* d_out, int out_size)
{
    const float* x = (const float*)d_in[0];
    const float* y = (const float*)d_in[1];
    float* out = (float*)d_out;

    // single-wave residency: opt in to 16KB dynamic smem and max shared carveout
    // so 7 blocks/SM fit (1024 blocks / 148 SMs = 6.92 -> one wave, no tail)
    cudaFuncSetAttribute(sinkhorn_phase,
                         cudaFuncAttributeMaxDynamicSharedMemorySize, SH_BYTES);
    cudaFuncSetAttribute(sinkhorn_phase,
                         cudaFuncAttributePreferredSharedMemoryCarveout, 100);

    dim3 grid(2 * NPTS / TPB, 4, BATCH);   // (32, 4, 8) = 1024 blocks

    // epsilon schedule: [diameter^2] + exp(arange(2ln2, 2ln0.05, 2ln0.5)) + [blur^2]
    const float eps_list[8] = {4.0f, 4.0f, 1.0f, 0.25f, 0.0625f,
                               0.015625f, 0.00390625f, 0.0025f};

    init_sq<<<128, 256>>>(x, y);

    // init at eps0=4 (h = log-weights only, no shift) -> buf0
    sinkhorn_phase<<<grid, TPB, SH_BYTES>>>(x, y, 4.0f, 0.0f, 0, 0);
    sinkhorn_combine<<<256, 256>>>(4.0f, 0, 0, 0, 0);

    int cur = 0;
    for (int i = 0; i < 8; i++) {
        sinkhorn_phase<<<grid, TPB, SH_BYTES>>>(x, y, eps_list[i], 1.0f, 1, cur);
        sinkhorn_combine<<<256, 256>>>(eps_list[i], 1, 1, cur, cur ^ 1);
        cur ^= 1;
    }
    // final extrapolation at blur^2, no averaging
    sinkhorn_phase<<<grid, TPB, SH_BYTES>>>(x, y, 0.0025f, 1.0f, 1, cur);
    sinkhorn_combine<<<256, 256>>>(0.0025f, 0, 1, cur, cur ^ 1);
    cur ^= 1;

    sinkhorn_reduce<<<BATCH, 256>>>(out, cur);
}

// round 12
// speedup vs baseline: 1.0409x; 1.0409x over previous
#include <cuda_runtime.h>
#include <math.h>

#define BATCH 8
#define NPTS  2048
#define HCOLS 1024            // columns per block (half split)
#define LOG2E 1.4426950408889634f
#define LN2   0.6931471805599453f
#define TPB   128
#define CHUNK 16
#define SH_BYTES (HCOLS * 16) // float4 per column pair-slot = 16 KB

// dual potentials, double-buffered: [buf][s: f_ba,g_ab,f_aa,g_bb][b*NPTS + i]
__device__ float g_dual[2][4][BATCH * NPTS];
// per-half PLAIN partial sums (shifted log2 domain): [half][s][b*NPTS + r]
__device__ float g_ps[2][4][BATCH * NPTS];
// 0.5*|p|^2 per point, [0]=x rows, [1]=y rows
__device__ float g_sq[2][BATCH * NPTS];

__device__ __forceinline__ float ex2(float x) {
    float r;
    asm("ex2.approx.ftz.f32 %0, %1;" : "=f"(r) : "f"(x));
    return r;
}
__device__ __forceinline__ unsigned long long pk2(float a, float b) {
    unsigned long long u;
    asm("mov.b64 %0, {%1,%2};" : "=l"(u) : "f"(a), "f"(b));
    return u;
}
__device__ __forceinline__ void upk2(unsigned long long u, float& a, float& b) {
    asm("mov.b64 {%0,%1}, %2;" : "=f"(a), "=f"(b) : "l"(u));
}
__device__ __forceinline__ unsigned long long fma2(unsigned long long a,
                                                   unsigned long long b,
                                                   unsigned long long c) {
    unsigned long long d;
    asm("fma.rn.f32x2 %0, %1, %2, %3;" : "=l"(d) : "l"(a), "l"(b), "l"(c));
    return d;
}
__device__ __forceinline__ unsigned long long add2(unsigned long long a,
                                                   unsigned long long b) {
    unsigned long long d;
    asm("add.rn.f32x2 %0, %1, %2;" : "=l"(d) : "l"(a), "l"(b));
    return d;
}

// softmin(eps,C,h)_i = -eps * LSE_j( h_j - C_ij/eps ), C_ij = .5|r_i|^2+.5|c_j|^2 - r.c
// log2 domain, PER-ROW SHIFT instead of online max:
//   S_i = (0.5|r_i|^2 - f_prev_i) * log2e / eps   (estimate of the row's log2-LSE)
//   ssum_i = sum_j 2^(arg_ij - S_i)   -- bounded since f drifts << 115*eps*ln2/phase
//   f_new_i = f_prev_i - eps*ln2*log2(ssum_i)
// Init phase (shift=0, eps=4): raw args lie in [-11.5,-10.7] log2 -> safe unshifted.
//
// The mainloop is SOFTWARE-PIPELINED: each iteration issues the NEXT chunk's
// 16 LDS (no consumer), then the CURRENT chunk's 16 ex2 + sum (covers LDS
// latency and keeps the MUFU port fed), then the FMA dots on the loaded data.
__global__ __launch_bounds__(TPB, 7) void sinkhorn_phase(
    const float* __restrict__ x, const float* __restrict__ y,
    float eps, float dual_scale, int shift, int rbuf)
{
    const int s = blockIdx.y;
    const int b = blockIdx.z;
    const int half   = blockIdx.x & 1;
    const int rowblk = blockIdx.x >> 1;
    const float* rows = (s == 0 || s == 2) ? x : y;
    const float* cols = (s == 0 || s == 3) ? y : x;
    const int di = (s == 0) ? 1 : (s == 1) ? 0 : s;
    const float* dual = g_dual[rbuf][di] + b * NPTS;
    const float* own  = g_dual[rbuf][s]  + b * NPTS;

    // pair-interleaved column table for packed FFMA2 (dynamic smem, 16 KB):
    // sh[2p]   = (c0a*sc, c0b*sc, c1a*sc, c1b*sc)
    // sh[2p+1] = (c2a*sc, c2b*sc, wa,     wb)      for columns (2p, 2p+1)
    extern __shared__ float4 sh[];

    const float inv_eps = 1.0f / eps;
    const float sc = inv_eps * LOG2E;
    const float logw = -logf((float)NPTS);
    const int col0 = half * HCOLS;

    for (int p = threadIdx.x; p < HCOLS / 2; p += TPB) {
        int j = col0 + 2 * p;
        const float* c = cols + (b * NPTS + j) * 3;
        float c0a = c[0], c1a = c[1], c2a = c[2];
        float c0b = c[3], c1b = c[4], c2b = c[5];
        float ha = logw + dual_scale * dual[j] * inv_eps;
        float hb = logw + dual_scale * dual[j + 1] * inv_eps;
        float wa = (ha - 0.5f * (c0a * c0a + c1a * c1a + c2a * c2a) * inv_eps) * LOG2E;
        float wb = (hb - 0.5f * (c0b * c0b + c1b * c1b + c2b * c2b) * inv_eps) * LOG2E;
        sh[2 * p]     = make_float4(c0a * sc, c0b * sc, c1a * sc, c1b * sc);
        sh[2 * p + 1] = make_float4(c2a * sc, c2b * sc, wa, wb);
    }
    __syncthreads();

    const int r = rowblk * TPB + threadIdx.x;
    const float* xr = rows + (b * NPTS + r) * 3;
    const float x0 = xr[0], x1 = xr[1], x2 = xr[2];
    const unsigned long long X0 = pk2(x0, x0);
    const unsigned long long X1 = pk2(x1, x1);
    const unsigned long long X2 = pk2(x2, x2);

    // per-row shift from previous dual value (always finite: zero-init / prior phase)
    const float sqr = 0.5f * (x0 * x0 + x1 * x1 + x2 * x2);
    const float S = shift ? (sqr - own[r]) * inv_eps * LOG2E : 0.0f;
    const unsigned long long nS2 = pk2(-S, -S);

    const ulonglong2* shu = (const ulonglong2*)sh;

    float ssum = 0.0f;

    // ---- prologue: load + dot chunk 0 ----
    float acur[CHUNK];
    {
        ulonglong2 A[CHUNK / 2], Bv[CHUNK / 2];
        #pragma unroll
        for (int k = 0; k < CHUNK / 2; k++) {
            A[k]  = shu[2 * k];
            Bv[k] = shu[2 * k + 1];
        }
        #pragma unroll
        for (int k = 0; k < CHUNK / 2; k++) {
            unsigned long long dk =
                fma2(X0, A[k].x, fma2(X1, A[k].y, fma2(X2, Bv[k].x, add2(Bv[k].y, nS2))));
            upk2(dk, acur[2 * k], acur[2 * k + 1]);
        }
    }

    #pragma unroll 1
    for (int j = CHUNK; j < HCOLS; j += CHUNK) {
        // (a) issue next chunk's loads -- no consumer yet, latency hidden below
        ulonglong2 A[CHUNK / 2], Bv[CHUNK / 2];
        #pragma unroll
        for (int k = 0; k < CHUNK / 2; k++) {
            A[k]  = shu[j + 2 * k];
            Bv[k] = shu[j + 2 * k + 1];
        }

        // (b) current chunk's exps + sum tree (MUFU busy while LDS in flight)
        float e[CHUNK];
        #pragma unroll
        for (int k = 0; k < CHUNK; k++) e[k] = ex2(acur[k]);
        float s0 = (e[0] + e[1]) + (e[2] + e[3]);
        float s1 = (e[4] + e[5]) + (e[6] + e[7]);
        float s2 = (e[8] + e[9]) + (e[10] + e[11]);
        float s3 = (e[12] + e[13]) + (e[14] + e[15]);
        ssum += (s0 + s1) + (s2 + s3);

        // (c) dots on arrived data -> becomes next iteration's acur
        #pragma unroll
        for (int k = 0; k < CHUNK / 2; k++) {
            unsigned long long dk =
                fma2(X0, A[k].x, fma2(X1, A[k].y, fma2(X2, Bv[k].x, add2(Bv[k].y, nS2))));
            upk2(dk, acur[2 * k], acur[2 * k + 1]);
        }
    }

    // ---- epilogue: consume last chunk ----
    {
        float e[CHUNK];
        #pragma unroll
        for (int k = 0; k < CHUNK; k++) e[k] = ex2(acur[k]);
        float s0 = (e[0] + e[1]) + (e[2] + e[3]);
        float s1 = (e[4] + e[5]) + (e[6] + e[7]);
        float s2 = (e[8] + e[9]) + (e[10] + e[11]);
        float s3 = (e[12] + e[13]) + (e[14] + e[15]);
        ssum += (s0 + s1) + (s2 + s3);
    }

    g_ps[half][s][b * NPTS + r] = ssum;
}

// merge the two halves, finish the softmin, apply averaging
__global__ void sinkhorn_combine(float eps, int do_avg, int shift, int rbuf, int wbuf)
{
    int idx = blockIdx.x * 256 + threadIdx.x;      // 4*BATCH*NPTS = 65536
    int s = idx >> 14;
    int rem = idx & 16383;                         // b*NPTS + r
    float sm = g_ps[0][s][rem] + g_ps[1][s][rem];
    float l2 = log2f(sm);
    float fp = g_dual[rbuf][s][rem];
    int rows_sel = (s == 0 || s == 2) ? 0 : 1;
    float fraw = shift ? fp - eps * LN2 * l2
                       : g_sq[rows_sel][rem] - eps * LN2 * l2;
    float o = do_avg ? 0.5f * (fp + fraw) : fraw;
    g_dual[wbuf][s][rem] = o;
}

__global__ void init_sq(const float* __restrict__ x, const float* __restrict__ y)
{
    int idx = blockIdx.x * 256 + threadIdx.x;      // 2*BATCH*NPTS = 32768
    int sel = idx >> 14;
    int rem = idx & 16383;
    const float* p = (sel ? y : x) + rem * 3;
    g_sq[sel][rem] = 0.5f * (p[0] * p[0] + p[1] * p[1] + p[2] * p[2]);
}

// out[b] = (1/N) * sum_i (f_ba - f_aa) + (1/M) * sum_j (g_ab - g_bb)
__global__ void sinkhorn_reduce(float* __restrict__ out, int buf)
{
    const int b = blockIdx.x;
    const int tid = threadIdx.x;
    float acc = 0.0f;
    for (int i = tid; i < NPTS; i += 256) {
        acc += g_dual[buf][0][b * NPTS + i] - g_dual[buf][2][b * NPTS + i];
        acc += g_dual[buf][1][b * NPTS + i] - g_dual[buf][3][b * NPTS + i];
    }
    __shared__ float red[256];
    red[tid] = acc;
    __syncthreads();
    for (int off = 128; off > 0; off >>= 1) {
        if (tid < off) red[tid] += red[tid + off];
        __syncthreads();
    }
    if (tid == 0) {
        float w = expf(-logf((float)NPTS));
        out[b] = red[0] * w;
    }
}

extern "C" void kernel_launch(void* const* d_in, const int* in_sizes, int n_in,
                              void* d_out, int out_size)
{
    const float* x = (const float*)d_in[0];
    const float* y = (const float*)d_in[1];
    float* out = (float*)d_out;

    cudaFuncSetAttribute(sinkhorn_phase,
                         cudaFuncAttributeMaxDynamicSharedMemorySize, SH_BYTES);
    cudaFuncSetAttribute(sinkhorn_phase,
                         cudaFuncAttributePreferredSharedMemoryCarveout, 100);

    dim3 grid(2 * NPTS / TPB, 4, BATCH);   // (32, 4, 8) = 1024 blocks

    // epsilon schedule: [diameter^2] + exp(arange(2ln2, 2ln0.05, 2ln0.5)) + [blur^2]
    const float eps_list[8] = {4.0f, 4.0f, 1.0f, 0.25f, 0.0625f,
                               0.015625f, 0.00390625f, 0.0025f};

    init_sq<<<128, 256>>>(x, y);

    // init at eps0=4 (h = log-weights only, no shift) -> buf0
    sinkhorn_phase<<<grid, TPB, SH_BYTES>>>(x, y, 4.0f, 0.0f, 0, 0);
    sinkhorn_combine<<<256, 256>>>(4.0f, 0, 0, 0, 0);

    int cur = 0;
    for (int i = 0; i < 8; i++) {
        sinkhorn_phase<<<grid, TPB, SH_BYTES>>>(x, y, eps_list[i], 1.0f, 1, cur);
        sinkhorn_combine<<<256, 256>>>(eps_list[i], 1, 1, cur, cur ^ 1);
        cur ^= 1;
    }
    // final extrapolation at blur^2, no averaging
    sinkhorn_phase<<<grid, TPB, SH_BYTES>>>(x, y, 0.0025f, 1.0f, 1, cur);
    sinkhorn_combine<<<256, 256>>>(0.0025f, 0, 1, cur, cur ^ 1);
    cur ^= 1;

    sinkhorn_reduce<<<BATCH, 256>>>(out, cur);
}

// round 13
// speedup vs baseline: 1.0542x; 1.0128x over previous
#include <cuda_runtime.h>
#include <math.h>

#define BATCH 8
#define NPTS  2048
#define HCOLS 1024            // columns per block (half split)
#define LOG2E 1.4426950408889634f
#define LN2   0.6931471805599453f
#define TPB   128
#define ROWS_PER_T 2
#define CHUNK 16
#define SH_BYTES (HCOLS * 16) // float4 per column pair-slot = 16 KB

// dual potentials, double-buffered: [buf][s: f_ba,g_ab,f_aa,g_bb][b*NPTS + i]
__device__ float g_dual[2][4][BATCH * NPTS];
// per-half PLAIN partial sums (shifted log2 domain): [half][s][b*NPTS + r]
__device__ float g_ps[2][4][BATCH * NPTS];
// 0.5*|p|^2 per point, [0]=x rows, [1]=y rows
__device__ float g_sq[2][BATCH * NPTS];

__device__ __forceinline__ float ex2(float x) {
    float r;
    asm("ex2.approx.ftz.f32 %0, %1;" : "=f"(r) : "f"(x));
    return r;
}
__device__ __forceinline__ unsigned long long pk2(float a, float b) {
    unsigned long long u;
    asm("mov.b64 %0, {%1,%2};" : "=l"(u) : "f"(a), "f"(b));
    return u;
}
__device__ __forceinline__ void upk2(unsigned long long u, float& a, float& b) {
    asm("mov.b64 {%0,%1}, %2;" : "=f"(a), "=f"(b) : "l"(u));
}
__device__ __forceinline__ unsigned long long fma2(unsigned long long a,
                                                   unsigned long long b,
                                                   unsigned long long c) {
    unsigned long long d;
    asm("fma.rn.f32x2 %0, %1, %2, %3;" : "=l"(d) : "l"(a), "l"(b), "l"(c));
    return d;
}
__device__ __forceinline__ unsigned long long add2(unsigned long long a,
                                                   unsigned long long b) {
    unsigned long long d;
    asm("add.rn.f32x2 %0, %1, %2;" : "=l"(d) : "l"(a), "l"(b));
    return d;
}

// softmin(eps,C,h)_i = -eps * LSE_j( h_j - C_ij/eps ), C_ij = .5|r_i|^2+.5|c_j|^2 - r.c
// log2 domain, PER-ROW SHIFT instead of online max:
//   S_i = (0.5|r_i|^2 - f_prev_i) * log2e / eps
//   ssum_i = sum_j 2^(arg_ij - S_i);  f_new_i = f_prev_i - eps*ln2*log2(ssum_i)
// Init phase (shift=0, eps=4): raw args lie in [-11.5,-10.7] log2 -> safe unshifted.
//
// TWO ROWS PER THREAD: every column vector loaded from shared feeds two dot
// chains -> LDS bytes per exp halved (the round-12 co-binder), MUFU the sole
// binder. Mainloop stays software-pipelined (next loads -> current exps -> dots).
__global__ __launch_bounds__(TPB, 4) void sinkhorn_phase(
    const float* __restrict__ x, const float* __restrict__ y,
    float eps, float dual_scale, int shift, int rbuf)
{
    const int s = blockIdx.y;
    const int b = blockIdx.z;
    const int half   = blockIdx.x & 1;
    const int rowblk = blockIdx.x >> 1;          // 0..7, 256 rows each
    const float* rows = (s == 0 || s == 2) ? x : y;
    const float* cols = (s == 0 || s == 3) ? y : x;
    const int di = (s == 0) ? 1 : (s == 1) ? 0 : s;
    const float* dual = g_dual[rbuf][di] + b * NPTS;
    const float* own  = g_dual[rbuf][s]  + b * NPTS;

    // pair-interleaved column table (dynamic smem, 16 KB):
    // sh[2p]   = (c0a*sc, c0b*sc, c1a*sc, c1b*sc)
    // sh[2p+1] = (c2a*sc, c2b*sc, wa,     wb)      for columns (2p, 2p+1)
    extern __shared__ float4 sh[];

    const float inv_eps = 1.0f / eps;
    const float sc = inv_eps * LOG2E;
    const float logw = -logf((float)NPTS);
    const int col0 = half * HCOLS;

    for (int p = threadIdx.x; p < HCOLS / 2; p += TPB) {
        int j = col0 + 2 * p;
        const float* c = cols + (b * NPTS + j) * 3;
        float c0a = c[0], c1a = c[1], c2a = c[2];
        float c0b = c[3], c1b = c[4], c2b = c[5];
        float ha = logw + dual_scale * dual[j] * inv_eps;
        float hb = logw + dual_scale * dual[j + 1] * inv_eps;
        float wa = (ha - 0.5f * (c0a * c0a + c1a * c1a + c2a * c2a) * inv_eps) * LOG2E;
        float wb = (hb - 0.5f * (c0b * c0b + c1b * c1b + c2b * c2b) * inv_eps) * LOG2E;
        sh[2 * p]     = make_float4(c0a * sc, c0b * sc, c1a * sc, c1b * sc);
        sh[2 * p + 1] = make_float4(c2a * sc, c2b * sc, wa, wb);
    }
    __syncthreads();

    const int r0 = rowblk * (TPB * ROWS_PER_T) + threadIdx.x;
    const int r1 = r0 + TPB;
    const float* xr0 = rows + (b * NPTS + r0) * 3;
    const float* xr1 = rows + (b * NPTS + r1) * 3;
    const float p00 = xr0[0], p01 = xr0[1], p02 = xr0[2];
    const float p10 = xr1[0], p11 = xr1[1], p12 = xr1[2];
    const unsigned long long X00 = pk2(p00, p00);
    const unsigned long long X01 = pk2(p01, p01);
    const unsigned long long X02 = pk2(p02, p02);
    const unsigned long long X10 = pk2(p10, p10);
    const unsigned long long X11 = pk2(p11, p11);
    const unsigned long long X12 = pk2(p12, p12);

    const float sq0 = 0.5f * (p00 * p00 + p01 * p01 + p02 * p02);
    const float sq1 = 0.5f * (p10 * p10 + p11 * p11 + p12 * p12);
    const float S0 = shift ? (sq0 - own[r0]) * inv_eps * LOG2E : 0.0f;
    const float S1 = shift ? (sq1 - own[r1]) * inv_eps * LOG2E : 0.0f;
    const unsigned long long nS0 = pk2(-S0, -S0);
    const unsigned long long nS1 = pk2(-S1, -S1);

    const ulonglong2* shu = (const ulonglong2*)sh;

    float ssum0 = 0.0f, ssum1 = 0.0f;

    // ---- prologue: load + dot chunk 0 (both rows) ----
    float a0[CHUNK], a1[CHUNK];
    {
        #pragma unroll
        for (int k = 0; k < CHUNK / 2; k++) {
            ulonglong2 A  = shu[2 * k];
            ulonglong2 Bv = shu[2 * k + 1];
            unsigned long long d0 =
                fma2(X00, A.x, fma2(X01, A.y, fma2(X02, Bv.x, add2(Bv.y, nS0))));
            unsigned long long d1 =
                fma2(X10, A.x, fma2(X11, A.y, fma2(X12, Bv.x, add2(Bv.y, nS1))));
            upk2(d0, a0[2 * k], a0[2 * k + 1]);
            upk2(d1, a1[2 * k], a1[2 * k + 1]);
        }
    }

    #pragma unroll 1
    for (int j = CHUNK; j < HCOLS; j += CHUNK) {
        // (a) next chunk's loads
        ulonglong2 A[CHUNK / 2], Bv[CHUNK / 2];
        #pragma unroll
        for (int k = 0; k < CHUNK / 2; k++) {
            A[k]  = shu[j + 2 * k];
            Bv[k] = shu[j + 2 * k + 1];
        }

        // (b) current chunk's exps + sums, both rows (MUFU saturating section)
        float e0[CHUNK], e1[CHUNK];
        #pragma unroll
        for (int k = 0; k < CHUNK; k++) e0[k] = ex2(a0[k]);
        #pragma unroll
        for (int k = 0; k < CHUNK; k++) e1[k] = ex2(a1[k]);
        {
            float t0 = (e0[0] + e0[1]) + (e0[2] + e0[3]);
            float t1 = (e0[4] + e0[5]) + (e0[6] + e0[7]);
            float t2 = (e0[8] + e0[9]) + (e0[10] + e0[11]);
            float t3 = (e0[12] + e0[13]) + (e0[14] + e0[15]);
            ssum0 += (t0 + t1) + (t2 + t3);
            float u0 = (e1[0] + e1[1]) + (e1[2] + e1[3]);
            float u1 = (e1[4] + e1[5]) + (e1[6] + e1[7]);
            float u2 = (e1[8] + e1[9]) + (e1[10] + e1[11]);
            float u3 = (e1[12] + e1[13]) + (e1[14] + e1[15]);
            ssum1 += (u0 + u1) + (u2 + u3);
        }

        // (c) dots on arrived data for both rows
        #pragma unroll
        for (int k = 0; k < CHUNK / 2; k++) {
            unsigned long long d0 =
                fma2(X00, A[k].x, fma2(X01, A[k].y, fma2(X02, Bv[k].x, add2(Bv[k].y, nS0))));
            unsigned long long d1 =
                fma2(X10, A[k].x, fma2(X11, A[k].y, fma2(X12, Bv[k].x, add2(Bv[k].y, nS1))));
            upk2(d0, a0[2 * k], a0[2 * k + 1]);
            upk2(d1, a1[2 * k], a1[2 * k + 1]);
        }
    }

    // ---- epilogue: consume last chunk ----
    {
        float e0[CHUNK], e1[CHUNK];
        #pragma unroll
        for (int k = 0; k < CHUNK; k++) e0[k] = ex2(a0[k]);
        #pragma unroll
        for (int k = 0; k < CHUNK; k++) e1[k] = ex2(a1[k]);
        float t0 = (e0[0] + e0[1]) + (e0[2] + e0[3]);
        float t1 = (e0[4] + e0[5]) + (e0[6] + e0[7]);
        float t2 = (e0[8] + e0[9]) + (e0[10] + e0[11]);
        float t3 = (e0[12] + e0[13]) + (e0[14] + e0[15]);
        ssum0 += (t0 + t1) + (t2 + t3);
        float u0 = (e1[0] + e1[1]) + (e1[2] + e1[3]);
        float u1 = (e1[4] + e1[5]) + (e1[6] + e1[7]);
        float u2 = (e1[8] + e1[9]) + (e1[10] + e1[11]);
        float u3 = (e1[12] + e1[13]) + (e1[14] + e1[15]);
        ssum1 += (u0 + u1) + (u2 + u3);
    }

    g_ps[half][s][b * NPTS + r0] = ssum0;
    g_ps[half][s][b * NPTS + r1] = ssum1;
}

// merge the two halves, finish the softmin, apply averaging
__global__ void sinkhorn_combine(float eps, int do_avg, int shift, int rbuf, int wbuf)
{
    int idx = blockIdx.x * 256 + threadIdx.x;      // 4*BATCH*NPTS = 65536
    int s = idx >> 14;
    int rem = idx & 16383;                         // b*NPTS + r
    float sm = g_ps[0][s][rem] + g_ps[1][s][rem];
    float l2 = log2f(sm);
    float fp = g_dual[rbuf][s][rem];
    int rows_sel = (s == 0 || s == 2) ? 0 : 1;
    float fraw = shift ? fp - eps * LN2 * l2
                       : g_sq[rows_sel][rem] - eps * LN2 * l2;
    float o = do_avg ? 0.5f * (fp + fraw) : fraw;
    g_dual[wbuf][s][rem] = o;
}

__global__ void init_sq(const float* __restrict__ x, const float* __restrict__ y)
{
    int idx = blockIdx.x * 256 + threadIdx.x;      // 2*BATCH*NPTS = 32768
    int sel = idx >> 14;
    int rem = idx & 16383;
    const float* p = (sel ? y : x) + rem * 3;
    g_sq[sel][rem] = 0.5f * (p[0] * p[0] + p[1] * p[1] + p[2] * p[2]);
}

// out[b] = (1/N) * sum_i (f_ba - f_aa) + (1/M) * sum_j (g_ab - g_bb)
__global__ void sinkhorn_reduce(float* __restrict__ out, int buf)
{
    const int b = blockIdx.x;
    const int tid = threadIdx.x;
    float acc = 0.0f;
    for (int i = tid; i < NPTS; i += 256) {
        acc += g_dual[buf][0][b * NPTS + i] - g_dual[buf][2][b * NPTS + i];
        acc += g_dual[buf][1][b * NPTS + i] - g_dual[buf][3][b * NPTS + i];
    }
    __shared__ float red[256];
    red[tid] = acc;
    __syncthreads();
    for (int off = 128; off > 0; off >>= 1) {
        if (tid < off) red[tid] += red[tid + off];
        __syncthreads();
    }
    if (tid == 0) {
        float w = expf(-logf((float)NPTS));
        out[b] = red[0] * w;
    }
}

extern "C" void kernel_launch(void* const* d_in, const int* in_sizes, int n_in,
                              void* d_out, int out_size)
{
    const float* x = (const float*)d_in[0];
    const float* y = (const float*)d_in[1];
    float* out = (float*)d_out;

    cudaFuncSetAttribute(sinkhorn_phase,
                         cudaFuncAttributeMaxDynamicSharedMemorySize, SH_BYTES);
    cudaFuncSetAttribute(sinkhorn_phase,
                         cudaFuncAttributePreferredSharedMemoryCarveout, 100);

    // 8 rowblks (256 rows each) x 2 halves, 4 softmins, 8 batches = 512 blocks
    dim3 grid(2 * NPTS / (TPB * ROWS_PER_T), 4, BATCH);

    // epsilon schedule: [diameter^2] + exp(arange(2ln2, 2ln0.05, 2ln0.5)) + [blur^2]
    const float eps_list[8] = {4.0f, 4.0f, 1.0f, 0.25f, 0.0625f,
                               0.015625f, 0.00390625f, 0.0025f};

    init_sq<<<128, 256>>>(x, y);

    // init at eps0=4 (h = log-weights only, no shift) -> buf0
    sinkhorn_phase<<<grid, TPB, SH_BYTES>>>(x, y, 4.0f, 0.0f, 0, 0);
    sinkhorn_combine<<<256, 256>>>(4.0f, 0, 0, 0, 0);

    int cur = 0;
    for (int i = 0; i < 8; i++) {
        sinkhorn_phase<<<grid, TPB, SH_BYTES>>>(x, y, eps_list[i], 1.0f, 1, cur);
        sinkhorn_combine<<<256, 256>>>(eps_list[i], 1, 1, cur, cur ^ 1);
        cur ^= 1;
    }
    // final extrapolation at blur^2, no averaging
    sinkhorn_phase<<<grid, TPB, SH_BYTES>>>(x, y, 0.0025f, 1.0f, 1, cur);
    sinkhorn_combine<<<256, 256>>>(0.0025f, 0, 1, cur, cur ^ 1);
    cur ^= 1;

    sinkhorn_reduce<<<BATCH, 256>>>(out, cur);
}

// round 14
// speedup vs baseline: 1.0556x; 1.0013x over previous
#include <cuda_runtime.h>
#include <math.h>

#define BATCH 8
#define NPTS  2048
#define HCOLS 1024            // columns per block (half split)
#define LOG2E 1.4426950408889634f
#define LN2   0.6931471805599453f
#define TPB   128
#define ROWS_PER_T 2
#define CHUNK 16
#define SH_BYTES (HCOLS * 16) // float4 per column pair-slot = 16 KB

// dual potentials, double-buffered: [buf][s: f_ba,g_ab,f_aa,g_bb][b*NPTS + i]
__device__ float g_dual[2][4][BATCH * NPTS];
// per-half PLAIN partial sums (shifted log2 domain): [half][s][b*NPTS + r]
__device__ float g_ps[2][4][BATCH * NPTS];
// 0.5*|p|^2 per point, [0]=x rows, [1]=y rows
__device__ float g_sq[2][BATCH * NPTS];

__device__ __forceinline__ float ex2(float x) {
    float r;
    asm("ex2.approx.ftz.f32 %0, %1;" : "=f"(r) : "f"(x));
    return r;
}
__device__ __forceinline__ unsigned long long pk2(float a, float b) {
    unsigned long long u;
    asm("mov.b64 %0, {%1,%2};" : "=l"(u) : "f"(a), "f"(b));
    return u;
}
__device__ __forceinline__ void upk2(unsigned long long u, float& a, float& b) {
    asm("mov.b64 {%0,%1}, %2;" : "=f"(a), "=f"(b) : "l"(u));
}
__device__ __forceinline__ unsigned long long fma2(unsigned long long a,
                                                   unsigned long long b,
                                                   unsigned long long c) {
    unsigned long long d;
    asm("fma.rn.f32x2 %0, %1, %2, %3;" : "=l"(d) : "l"(a), "l"(b), "l"(c));
    return d;
}
__device__ __forceinline__ unsigned long long add2(unsigned long long a,
                                                   unsigned long long b) {
    unsigned long long d;
    asm("add.rn.f32x2 %0, %1, %2;" : "=l"(d) : "l"(a), "l"(b));
    return d;
}

// softmin(eps,C,h)_i = -eps * LSE_j( h_j - C_ij/eps ), C_ij = .5|r_i|^2+.5|c_j|^2 - r.c
// log2 domain, PER-ROW SHIFT instead of online max:
//   S_i = (0.5|r_i|^2 - f_prev_i) * log2e / eps
//   ssum_i = sum_j 2^(arg_ij - S_i);  f_new_i = f_prev_i - eps*ln2*log2(ssum_i)
// Init phase (shift=0, eps=4): raw args lie in [-11.5,-10.7] log2 -> safe unshifted.
//
// TWO ROWS PER THREAD: every column vector loaded from shared feeds two dot
// chains -> LDS bytes per exp halved (the round-12 co-binder), MUFU the sole
// binder. Mainloop stays software-pipelined (next loads -> current exps -> dots).
__global__ __launch_bounds__(TPB, 4) void sinkhorn_phase(
    const float* __restrict__ x, const float* __restrict__ y,
    float eps, float dual_scale, int shift, int rbuf)
{
    const int s = blockIdx.y;
    const int b = blockIdx.z;
    const int half   = blockIdx.x & 1;
    const int rowblk = blockIdx.x >> 1;          // 0..7, 256 rows each
    const float* rows = (s == 0 || s == 2) ? x : y;
    const float* cols = (s == 0 || s == 3) ? y : x;
    const int di = (s == 0) ? 1 : (s == 1) ? 0 : s;
    const float* dual = g_dual[rbuf][di] + b * NPTS;
    const float* own  = g_dual[rbuf][s]  + b * NPTS;

    // pair-interleaved column table (dynamic smem, 16 KB):
    // sh[2p]   = (c0a*sc, c0b*sc, c1a*sc, c1b*sc)
    // sh[2p+1] = (c2a*sc, c2b*sc, wa,     wb)      for columns (2p, 2p+1)
    extern __shared__ float4 sh[];

    const float inv_eps = 1.0f / eps;
    const float sc = inv_eps * LOG2E;
    const float logw = -logf((float)NPTS);
    const int col0 = half * HCOLS;

    for (int p = threadIdx.x; p < HCOLS / 2; p += TPB) {
        int j = col0 + 2 * p;
        const float* c = cols + (b * NPTS + j) * 3;
        float c0a = c[0], c1a = c[1], c2a = c[2];
        float c0b = c[3], c1b = c[4], c2b = c[5];
        float ha = logw + dual_scale * dual[j] * inv_eps;
        float hb = logw + dual_scale * dual[j + 1] * inv_eps;
        float wa = (ha - 0.5f * (c0a * c0a + c1a * c1a + c2a * c2a) * inv_eps) * LOG2E;
        float wb = (hb - 0.5f * (c0b * c0b + c1b * c1b + c2b * c2b) * inv_eps) * LOG2E;
        sh[2 * p]     = make_float4(c0a * sc, c0b * sc, c1a * sc, c1b * sc);
        sh[2 * p + 1] = make_float4(c2a * sc, c2b * sc, wa, wb);
    }
    __syncthreads();

    const int r0 = rowblk * (TPB * ROWS_PER_T) + threadIdx.x;
    const int r1 = r0 + TPB;
    const float* xr0 = rows + (b * NPTS + r0) * 3;
    const float* xr1 = rows + (b * NPTS + r1) * 3;
    const float p00 = xr0[0], p01 = xr0[1], p02 = xr0[2];
    const float p10 = xr1[0], p11 = xr1[1], p12 = xr1[2];
    const unsigned long long X00 = pk2(p00, p00);
    const unsigned long long X01 = pk2(p01, p01);
    const unsigned long long X02 = pk2(p02, p02);
    const unsigned long long X10 = pk2(p10, p10);
    const unsigned long long X11 = pk2(p11, p11);
    const unsigned long long X12 = pk2(p12, p12);

    const float sq0 = 0.5f * (p00 * p00 + p01 * p01 + p02 * p02);
    const float sq1 = 0.5f * (p10 * p10 + p11 * p11 + p12 * p12);
    const float S0 = shift ? (sq0 - own[r0]) * inv_eps * LOG2E : 0.0f;
    const float S1 = shift ? (sq1 - own[r1]) * inv_eps * LOG2E : 0.0f;
    const unsigned long long nS0 = pk2(-S0, -S0);
    const unsigned long long nS1 = pk2(-S1, -S1);

    const ulonglong2* shu = (const ulonglong2*)sh;

    float ssum0 = 0.0f, ssum1 = 0.0f;

    // ---- prologue: load + dot chunk 0 (both rows) ----
    float a0[CHUNK], a1[CHUNK];
    {
        #pragma unroll
        for (int k = 0; k < CHUNK / 2; k++) {
            ulonglong2 A  = shu[2 * k];
            ulonglong2 Bv = shu[2 * k + 1];
            unsigned long long d0 =
                fma2(X00, A.x, fma2(X01, A.y, fma2(X02, Bv.x, add2(Bv.y, nS0))));
            unsigned long long d1 =
                fma2(X10, A.x, fma2(X11, A.y, fma2(X12, Bv.x, add2(Bv.y, nS1))));
            upk2(d0, a0[2 * k], a0[2 * k + 1]);
            upk2(d1, a1[2 * k], a1[2 * k + 1]);
        }
    }

    #pragma unroll 1
    for (int j = CHUNK; j < HCOLS; j += CHUNK) {
        // (a) next chunk's loads
        ulonglong2 A[CHUNK / 2], Bv[CHUNK / 2];
        #pragma unroll
        for (int k = 0; k < CHUNK / 2; k++) {
            A[k]  = shu[j + 2 * k];
            Bv[k] = shu[j + 2 * k + 1];
        }

        // (b) current chunk's exps + sums, both rows (MUFU saturating section)
        float e0[CHUNK], e1[CHUNK];
        #pragma unroll
        for (int k = 0; k < CHUNK; k++) e0[k] = ex2(a0[k]);
        #pragma unroll
        for (int k = 0; k < CHUNK; k++) e1[k] = ex2(a1[k]);
        {
            float t0 = (e0[0] + e0[1]) + (e0[2] + e0[3]);
            float t1 = (e0[4] + e0[5]) + (e0[6] + e0[7]);
            float t2 = (e0[8] + e0[9]) + (e0[10] + e0[11]);
            float t3 = (e0[12] + e0[13]) + (e0[14] + e0[15]);
            ssum0 += (t0 + t1) + (t2 + t3);
            float u0 = (e1[0] + e1[1]) + (e1[2] + e1[3]);
            float u1 = (e1[4] + e1[5]) + (e1[6] + e1[7]);
            float u2 = (e1[8] + e1[9]) + (e1[10] + e1[11]);
            float u3 = (e1[12] + e1[13]) + (e1[14] + e1[15]);
            ssum1 += (u0 + u1) + (u2 + u3);
        }

        // (c) dots on arrived data for both rows
        #pragma unroll
        for (int k = 0; k < CHUNK / 2; k++) {
            unsigned long long d0 =
                fma2(X00, A[k].x, fma2(X01, A[k].y, fma2(X02, Bv[k].x, add2(Bv[k].y, nS0))));
            unsigned long long d1 =
                fma2(X10, A[k].x, fma2(X11, A[k].y, fma2(X12, Bv[k].x, add2(Bv[k].y, nS1))));
            upk2(d0, a0[2 * k], a0[2 * k + 1]);
            upk2(d1, a1[2 * k], a1[2 * k + 1]);
        }
    }

    // ---- epilogue: consume last chunk ----
    {
        float e0[CHUNK], e1[CHUNK];
        #pragma unroll
        for (int k = 0; k < CHUNK; k++) e0[k] = ex2(a0[k]);
        #pragma unroll
        for (int k = 0; k < CHUNK; k++) e1[k] = ex2(a1[k]);
        float t0 = (e0[0] + e0[1]) + (e0[2] + e0[3]);
        float t1 = (e0[4] + e0[5]) + (e0[6] + e0[7]);
        float t2 = (e0[8] + e0[9]) + (e0[10] + e0[11]);
        float t3 = (e0[12] + e0[13]) + (e0[14] + e0[15]);
        ssum0 += (t0 + t1) + (t2 + t3);
        float u0 = (e1[0] + e1[1]) + (e1[2] + e1[3]);
        float u1 = (e1[4] + e1[5]) + (e1[6] + e1[7]);
        float u2 = (e1[8] + e1[9]) + (e1[10] + e1[11]);
        float u3 = (e1[12] + e1[13]) + (e1[14] + e1[15]);
        ssum1 += (u0 + u1) + (u2 + u3);
    }

    g_ps[half][s][b * NPTS + r0] = ssum0;
    g_ps[half][s][b * NPTS + r1] = ssum1;
}

// merge the two halves, finish the softmin, apply averaging
__global__ void sinkhorn_combine(float eps, int do_avg, int shift, int rbuf, int wbuf)
{
    int idx = blockIdx.x * 256 + threadIdx.x;      // 4*BATCH*NPTS = 65536
    int s = idx >> 14;
    int rem = idx & 16383;                         // b*NPTS + r
    float sm = g_ps[0][s][rem] + g_ps[1][s][rem];
    float l2 = log2f(sm);
    float fp = g_dual[rbuf][s][rem];
    int rows_sel = (s == 0 || s == 2) ? 0 : 1;
    float fraw = shift ? fp - eps * LN2 * l2
                       : g_sq[rows_sel][rem] - eps * LN2 * l2;
    float o = do_avg ? 0.5f * (fp + fraw) : fraw;
    g_dual[wbuf][s][rem] = o;
}

__global__ void init_sq(const float* __restrict__ x, const float* __restrict__ y)
{
    int idx = blockIdx.x * 256 + threadIdx.x;      // 2*BATCH*NPTS = 32768
    int sel = idx >> 14;
    int rem = idx & 16383;
    const float* p = (sel ? y : x) + rem * 3;
    g_sq[sel][rem] = 0.5f * (p[0] * p[0] + p[1] * p[1] + p[2] * p[2]);
}

// out[b] = (1/N) * sum_i (f_ba - f_aa) + (1/M) * sum_j (g_ab - g_bb)
__global__ void sinkhorn_reduce(float* __restrict__ out, int buf)
{
    const int b = blockIdx.x;
    const int tid = threadIdx.x;
    float acc = 0.0f;
    for (int i = tid; i < NPTS; i += 256) {
        acc += g_dual[buf][0][b * NPTS + i] - g_dual[buf][2][b * NPTS + i];
        acc += g_dual[buf][1][b * NPTS + i] - g_dual[buf][3][b * NPTS + i];
    }
    __shared__ float red[256];
    red[tid] = acc;
    __syncthreads();
    for (int off = 128; off > 0; off >>= 1) {
        if (tid < off) red[tid] += red[tid + off];
        __syncthreads();
    }
    if (tid == 0) {
        float w = expf(-logf((float)NPTS));
        out[b] = red[0] * w;
    }
}

extern "C" void kernel_launch(void* const* d_in, const int* in_sizes, int n_in,
                              void* d_out, int out_size)
{
    const float* x = (const float*)d_in[0];
    const float* y = (const float*)d_in[1];
    float* out = (float*)d_out;

    cudaFuncSetAttribute(sinkhorn_phase,
                         cudaFuncAttributeMaxDynamicSharedMemorySize, SH_BYTES);
    cudaFuncSetAttribute(sinkhorn_phase,
                         cudaFuncAttributePreferredSharedMemoryCarveout, 100);

    // 8 rowblks (256 rows each) x 2 halves, 4 softmins, 8 batches = 512 blocks
    dim3 grid(2 * NPTS / (TPB * ROWS_PER_T), 4, BATCH);

    // epsilon schedule: [diameter^2] + exp(arange(2ln2, 2ln0.05, 2ln0.5)) + [blur^2]
    const float eps_list[8] = {4.0f, 4.0f, 1.0f, 0.25f, 0.0625f,
                               0.015625f, 0.00390625f, 0.0025f};

    init_sq<<<128, 256>>>(x, y);

    // init at eps0=4 (h = log-weights only, no shift) -> buf0
    sinkhorn_phase<<<grid, TPB, SH_BYTES>>>(x, y, 4.0f, 0.0f, 0, 0);
    sinkhorn_combine<<<256, 256>>>(4.0f, 0, 0, 0, 0);

    int cur = 0;
    for (int i = 0; i < 8; i++) {
        sinkhorn_phase<<<grid, TPB, SH_BYTES>>>(x, y, eps_list[i], 1.0f, 1, cur);
        sinkhorn_combine<<<256, 256>>>(eps_list[i], 1, 1, cur, cur ^ 1);
        cur ^= 1;
    }
    // final extrapolation at blur^2, no averaging
    sinkhorn_phase<<<grid, TPB, SH_BYTES>>>(x, y, 0.0025f, 1.0f, 1, cur);
    sinkhorn_combine<<<256, 256>>>(0.0025f, 0, 1, cur, cur ^ 1);
    cur ^= 1;

    sinkhorn_reduce<<<BATCH, 256>>>(out, cur);
}

// round 15
// speedup vs baseline: 1.0901x; 1.0327x over previous
#include <cuda_runtime.h>
#include <math.h>

#define BATCH 8
#define NPTS  2048
#define HCOLS 1024            // columns per block (half split)
#define LOG2E 1.4426950408889634f
#define LN2   0.6931471805599453f
#define TPB   128
#define ROWS_PER_T 2
#define CHUNK 16
#define SH_BYTES (HCOLS * 16) // float4 per column pair-slot = 16 KB

// dual potentials, double-buffered: [buf][s: f_ba,g_ab,f_aa,g_bb][b*NPTS + i]
__device__ float g_dual[2][4][BATCH * NPTS];
// partial sums, double-buffered: [buf][half][s][b*NPTS + r]
__device__ float g_ps[2][2][4][BATCH * NPTS];

__device__ __forceinline__ float ex2(float x) {
    float r;
    asm("ex2.approx.ftz.f32 %0, %1;" : "=f"(r) : "f"(x));
    return r;
}
__device__ __forceinline__ float lg2(float x) {
    float r;
    asm("lg2.approx.f32 %0, %1;" : "=f"(r) : "f"(x));
    return r;
}
__device__ __forceinline__ unsigned long long pk2(float a, float b) {
    unsigned long long u;
    asm("mov.b64 %0, {%1,%2};" : "=l"(u) : "f"(a), "f"(b));
    return u;
}
__device__ __forceinline__ void upk2(unsigned long long u, float& a, float& b) {
    asm("mov.b64 {%0,%1}, %2;" : "=f"(a), "=f"(b) : "l"(u));
}
__device__ __forceinline__ unsigned long long fma2(unsigned long long a,
                                                   unsigned long long b,
                                                   unsigned long long c) {
    unsigned long long d;
    asm("fma.rn.f32x2 %0, %1, %2, %3;" : "=l"(d) : "l"(a), "l"(b), "l"(c));
    return d;
}
__device__ __forceinline__ unsigned long long add2(unsigned long long a,
                                                   unsigned long long b) {
    unsigned long long d;
    asm("add.rn.f32x2 %0, %1, %2;" : "=l"(d) : "l"(a), "l"(b));
    return d;
}

// softmin(eps,C,h)_i = -eps * LSE_j( h_j - C_ij/eps ), log2 domain, per-row shift.
// FUSED COMBINE: the previous phase's combine  f_prev = base - pcoef*log2(ps0+ps1)
// (base = g_dual[rbuf] for mode=2, base = 0.5|p|^2 for mode=1 init-combine) is
// reconstructed inline for this block's columns (partner dual di) and own rows.
// Own-row f_prev is written to g_dual[wbuf] for the next phase (both halves write
// identical values). mode=0 is the very first phase: uniform weights, no shift.
__global__ __launch_bounds__(TPB, 4) void sinkhorn_phase(
    const float* __restrict__ x, const float* __restrict__ y,
    float eps, float pcoef, int mode, int rbuf, int wbuf, int psr, int psw)
{
    const int s = blockIdx.y;
    const int b = blockIdx.z;
    const int half   = blockIdx.x & 1;
    const int rowblk = blockIdx.x >> 1;          // 0..7, 256 rows each
    const float* rows = (s == 0 || s == 2) ? x : y;
    const float* cols = (s == 0 || s == 3) ? y : x;
    const int di = (s == 0) ? 1 : (s == 1) ? 0 : s;

    // pair-interleaved column table (dynamic smem, 16 KB):
    // sh[2p]   = (c0a*sc, c0b*sc, c1a*sc, c1b*sc)
    // sh[2p+1] = (c2a*sc, c2b*sc, wa,     wb)      for columns (2p, 2p+1)
    extern __shared__ float4 sh[];

    const float inv_eps = 1.0f / eps;
    const float sc = inv_eps * LOG2E;
    const float logw = -logf((float)NPTS);
    const int col0 = half * HCOLS;

    for (int p = threadIdx.x; p < HCOLS / 2; p += TPB) {
        int j = col0 + 2 * p;
        int idx = b * NPTS + j;
        const float* c = cols + idx * 3;
        float c0a = c[0], c1a = c[1], c2a = c[2];
        float c0b = c[3], c1b = c[4], c2b = c[5];
        float sqa = 0.5f * (c0a * c0a + c1a * c1a + c2a * c2a);
        float sqb = 0.5f * (c0b * c0b + c1b * c1b + c2b * c2b);
        float ha = logw, hb = logw;
        if (mode != 0) {
            float pa = g_ps[psr][0][di][idx]     + g_ps[psr][1][di][idx];
            float pb = g_ps[psr][0][di][idx + 1] + g_ps[psr][1][di][idx + 1];
            float base_a = (mode == 1) ? sqa : g_dual[rbuf][di][idx];
            float base_b = (mode == 1) ? sqb : g_dual[rbuf][di][idx + 1];
            float fa = base_a - pcoef * lg2(pa);
            float fb = base_b - pcoef * lg2(pb);
            ha += fa * inv_eps;
            hb += fb * inv_eps;
        }
        float wa = (ha - sqa * inv_eps) * LOG2E;
        float wb = (hb - sqb * inv_eps) * LOG2E;
        sh[2 * p]     = make_float4(c0a * sc, c0b * sc, c1a * sc, c1b * sc);
        sh[2 * p + 1] = make_float4(c2a * sc, c2b * sc, wa, wb);
    }

    // own rows: inline combine -> shift, and publish duals for next phase
    const int r0 = rowblk * (TPB * ROWS_PER_T) + threadIdx.x;
    const int r1 = r0 + TPB;
    const int i0 = b * NPTS + r0, i1 = b * NPTS + r1;
    const float* xr0 = rows + i0 * 3;
    const float* xr1 = rows + i1 * 3;
    const float p00 = xr0[0], p01 = xr0[1], p02 = xr0[2];
    const float p10 = xr1[0], p11 = xr1[1], p12 = xr1[2];
    const float sq0 = 0.5f * (p00 * p00 + p01 * p01 + p02 * p02);
    const float sq1 = 0.5f * (p10 * p10 + p11 * p11 + p12 * p12);

    float S0 = 0.0f, S1 = 0.0f;
    if (mode != 0) {
        float pa = g_ps[psr][0][s][i0] + g_ps[psr][1][s][i0];
        float pb = g_ps[psr][0][s][i1] + g_ps[psr][1][s][i1];
        float base0 = (mode == 1) ? sq0 : g_dual[rbuf][s][i0];
        float base1 = (mode == 1) ? sq1 : g_dual[rbuf][s][i1];
        float f0 = base0 - pcoef * lg2(pa);
        float f1 = base1 - pcoef * lg2(pb);
        g_dual[wbuf][s][i0] = f0;   // both halves write identical values: benign
        g_dual[wbuf][s][i1] = f1;
        S0 = (sq0 - f0) * inv_eps * LOG2E;
        S1 = (sq1 - f1) * inv_eps * LOG2E;
    }
    __syncthreads();

    const unsigned long long X00 = pk2(p00, p00), X01 = pk2(p01, p01), X02 = pk2(p02, p02);
    const unsigned long long X10 = pk2(p10, p10), X11 = pk2(p11, p11), X12 = pk2(p12, p12);
    const unsigned long long nS0 = pk2(-S0, -S0), nS1 = pk2(-S1, -S1);

    const ulonglong2* shu = (const ulonglong2*)sh;

    float ssum0 = 0.0f, ssum1 = 0.0f;

    // ---- prologue: load + dot chunk 0 (both rows) ----
    float a0[CHUNK], a1[CHUNK];
    {
        #pragma unroll
        for (int k = 0; k < CHUNK / 2; k++) {
            ulonglong2 A  = shu[2 * k];
            ulonglong2 Bv = shu[2 * k + 1];
            unsigned long long d0 =
                fma2(X00, A.x, fma2(X01, A.y, fma2(X02, Bv.x, add2(Bv.y, nS0))));
            unsigned long long d1 =
                fma2(X10, A.x, fma2(X11, A.y, fma2(X12, Bv.x, add2(Bv.y, nS1))));
            upk2(d0, a0[2 * k], a0[2 * k + 1]);
            upk2(d1, a1[2 * k], a1[2 * k + 1]);
        }
    }

    #pragma unroll 1
    for (int j = CHUNK; j < HCOLS; j += CHUNK) {
        // (a) next chunk's loads
        ulonglong2 A[CHUNK / 2], Bv[CHUNK / 2];
        #pragma unroll
        for (int k = 0; k < CHUNK / 2; k++) {
            A[k]  = shu[j + 2 * k];
            Bv[k] = shu[j + 2 * k + 1];
        }

        // (b) current chunk's exps + sums, both rows (MUFU saturating section)
        float e0[CHUNK], e1[CHUNK];
        #pragma unroll
        for (int k = 0; k < CHUNK; k++) e0[k] = ex2(a0[k]);
        #pragma unroll
        for (int k = 0; k < CHUNK; k++) e1[k] = ex2(a1[k]);
        {
            float t0 = (e0[0] + e0[1]) + (e0[2] + e0[3]);
            float t1 = (e0[4] + e0[5]) + (e0[6] + e0[7]);
            float t2 = (e0[8] + e0[9]) + (e0[10] + e0[11]);
            float t3 = (e0[12] + e0[13]) + (e0[14] + e0[15]);
            ssum0 += (t0 + t1) + (t2 + t3);
            float u0 = (e1[0] + e1[1]) + (e1[2] + e1[3]);
            float u1 = (e1[4] + e1[5]) + (e1[6] + e1[7]);
            float u2 = (e1[8] + e1[9]) + (e1[10] + e1[11]);
            float u3 = (e1[12] + e1[13]) + (e1[14] + e1[15]);
            ssum1 += (u0 + u1) + (u2 + u3);
        }

        // (c) dots on arrived data for both rows
        #pragma unroll
        for (int k = 0; k < CHUNK / 2; k++) {
            unsigned long long d0 =
                fma2(X00, A[k].x, fma2(X01, A[k].y, fma2(X02, Bv[k].x, add2(Bv[k].y, nS0))));
            unsigned long long d1 =
                fma2(X10, A[k].x, fma2(X11, A[k].y, fma2(X12, Bv[k].x, add2(Bv[k].y, nS1))));
            upk2(d0, a0[2 * k], a0[2 * k + 1]);
            upk2(d1, a1[2 * k], a1[2 * k + 1]);
        }
    }

    // ---- epilogue: consume last chunk ----
    {
        float e0[CHUNK], e1[CHUNK];
        #pragma unroll
        for (int k = 0; k < CHUNK; k++) e0[k] = ex2(a0[k]);
        #pragma unroll
        for (int k = 0; k < CHUNK; k++) e1[k] = ex2(a1[k]);
        float t0 = (e0[0] + e0[1]) + (e0[2] + e0[3]);
        float t1 = (e0[4] + e0[5]) + (e0[6] + e0[7]);
        float t2 = (e0[8] + e0[9]) + (e0[10] + e0[11]);
        float t3 = (e0[12] + e0[13]) + (e0[14] + e0[15]);
        ssum0 += (t0 + t1) + (t2 + t3);
        float u0 = (e1[0] + e1[1]) + (e1[2] + e1[3]);
        float u1 = (e1[4] + e1[5]) + (e1[6] + e1[7]);
        float u2 = (e1[8] + e1[9]) + (e1[10] + e1[11]);
        float u3 = (e1[12] + e1[13]) + (e1[14] + e1[15]);
        ssum1 += (u0 + u1) + (u2 + u3);
    }

    g_ps[psw][half][s][i0] = ssum0;
    g_ps[psw][half][s][i1] = ssum1;
}

// final combine (extrapolation, no averaging) + divergence reduction
// out[b] = (1/N) * sum_i [ (f_ba - f_aa) + (g_ab - g_bb) ]
__global__ void sinkhorn_reduce(float* __restrict__ out, int db, int psb, float pcoef)
{
    const int b = blockIdx.x;
    const int tid = threadIdx.x;
    float acc = 0.0f;
    for (int i = tid; i < NPTS; i += 256) {
        int idx = b * NPTS + i;
        float f0 = g_dual[db][0][idx] - pcoef * lg2(g_ps[psb][0][0][idx] + g_ps[psb][1][0][idx]);
        float f1 = g_dual[db][1][idx] - pcoef * lg2(g_ps[psb][0][1][idx] + g_ps[psb][1][1][idx]);
        float f2 = g_dual[db][2][idx] - pcoef * lg2(g_ps[psb][0][2][idx] + g_ps[psb][1][2][idx]);
        float f3 = g_dual[db][3][idx] - pcoef * lg2(g_ps[psb][0][3][idx] + g_ps[psb][1][3][idx]);
        acc += (f0 - f2) + (f1 - f3);
    }
    __shared__ float red[256];
    red[tid] = acc;
    __syncthreads();
    for (int off = 128; off > 0; off >>= 1) {
        if (tid < off) red[tid] += red[tid + off];
        __syncthreads();
    }
    if (tid == 0) out[b] = red[0] * (1.0f / (float)NPTS);
}

extern "C" void kernel_launch(void* const* d_in, const int* in_sizes, int n_in,
                              void* d_out, int out_size)
{
    const float* x = (const float*)d_in[0];
    const float* y = (const float*)d_in[1];
    float* out = (float*)d_out;

    cudaFuncSetAttribute(sinkhorn_phase,
                         cudaFuncAttributeMaxDynamicSharedMemorySize, SH_BYTES);
    cudaFuncSetAttribute(sinkhorn_phase,
                         cudaFuncAttributePreferredSharedMemoryCarveout, 100);

    // 8 rowblks (256 rows each) x 2 halves, 4 softmins, 8 batches = 512 blocks
    dim3 grid(2 * NPTS / (TPB * ROWS_PER_T), 4, BATCH);

    // epsilon schedule: [diameter^2] + exp(arange(2ln2, 2ln0.05, 2ln0.5)) + [blur^2]
    const float eps_list[8] = {4.0f, 4.0f, 1.0f, 0.25f, 0.0625f,
                               0.015625f, 0.00390625f, 0.0025f};

    // phase 0: init at eps0=4, uniform weights, no shift -> ps[0]
    sinkhorn_phase<<<grid, TPB, SH_BYTES>>>(x, y, 4.0f, 0.0f, 0, 0, 0, 0, 0);
    int ps = 0;   // buffer holding latest partials
    int db = 0;   // buffer holding latest duals

    // phase 1: weights from init-combine (base = sq, pcoef = eps0*ln2);
    // writes f_0 duals to g_dual[0]
    sinkhorn_phase<<<grid, TPB, SH_BYTES>>>(x, y, eps_list[0], 4.0f * LN2,
                                            1, 0, 0, ps, ps ^ 1);
    ps ^= 1;
    db = 0;

    // phases 2..8: averaged combine of previous phase (pcoef = 0.5*prev_eps*ln2)
    float prev_eps = eps_list[0];
    for (int i = 1; i < 8; i++) {
        sinkhorn_phase<<<grid, TPB, SH_BYTES>>>(x, y, eps_list[i],
                                                0.5f * prev_eps * LN2,
                                                2, db, db ^ 1, ps, ps ^ 1);
        ps ^= 1;
        db ^= 1;
        prev_eps = eps_list[i];
    }

    // phase 9: final extrapolation at blur^2 (weights from averaged f_8)
    sinkhorn_phase<<<grid, TPB, SH_BYTES>>>(x, y, 0.0025f,
                                            0.5f * prev_eps * LN2,
                                            2, db, db ^ 1, ps, ps ^ 1);
    ps ^= 1;
    db ^= 1;

    // reduce does the last (non-averaged) combine inline: pcoef = eps_last*ln2
    sinkhorn_reduce<<<BATCH, 256>>>(out, db, ps, 0.0025f * LN2);
}